// round 15
// baseline (speedup 1.0000x reference)
#include <cuda_runtime.h>
#include <cuda_bf16.h>
#include <math.h>
#include <stdint.h>
#include <cstdint>

#define G_N   20000
#define T_N   1536
#define D_N   512
#define B_N   256
#define K_TOP 32
#define NTGT  44      // radix-select target rank (Gamma(12) gap margin over 32)
#define CCAP  48      // candidate capacity; 24-bit threshold => collected ~ NTGT+0
#define NH    4       // histogram copies (warp pairs)
#define RGRID 148     // persistent rescore blocks (1 per SM)

// ---------------- device scratch (static: no allocation at runtime) ----------------
__device__ float          g_sim[(size_t)G_N * T_N];   // [G, T] screening similarity
__device__ float          g_tfT[T_N * B_N];           // tf_expr transposed [T, B]
__device__ int            g_tki[G_N * K_TOP];
__device__ float          g_tkw[G_N * K_TOP];
__device__ __nv_bfloat16  g_Ah[(size_t)G_N * D_N];    // tg_dec bf16
__device__ __nv_bfloat16  g_Bh[(size_t)T_N * D_N];    // tf_base bf16
__device__ int            g_cand[G_N * CCAP];         // per-row candidate indices
__device__ int            g_cnt[G_N];                 // per-row candidate count
__device__ float          g_mv[G_N];                  // per-row approx max
__device__ float          g_Zv[G_N];                  // per-row approx Z

// ============================================================================
// PTX helpers (baseline PTX only — harness ptxas targets plain sm_103;
// tcgen05 is rejected there, mma.sync/cp.async/ldmatrix are sm_80+ baseline)
// ============================================================================
__device__ __forceinline__ uint32_t smem_u32(const void* p) {
    uint32_t a;
    asm("{ .reg .u64 t; cvta.to.shared.u64 t, %1; cvt.u32.u64 %0, t; }"
        : "=r"(a) : "l"(p));
    return a;
}
__device__ __forceinline__ void cpa16(uint32_t d, const void* s, bool v) {
    int sz = v ? 16 : 0;
    asm volatile("cp.async.cg.shared.global [%0], [%1], 16, %2;"
                 :: "r"(d), "l"(s), "r"(sz));
}
__device__ __forceinline__ void cpa_commit() {
    asm volatile("cp.async.commit_group;" ::: "memory");
}
__device__ __forceinline__ void cpa_wait1() {
    asm volatile("cp.async.wait_group 1;" ::: "memory");
}
__device__ __forceinline__ void cpa_wait2() {
    asm volatile("cp.async.wait_group 2;" ::: "memory");
}
__device__ __forceinline__ void cpa_wait0() {
    asm volatile("cp.async.wait_group 0;" ::: "memory");
}
__device__ __forceinline__ void ldsm_x4(uint32_t& r0, uint32_t& r1,
                                        uint32_t& r2, uint32_t& r3, uint32_t a) {
    asm volatile("ldmatrix.sync.aligned.m8n8.x4.shared.b16 {%0,%1,%2,%3}, [%4];"
                 : "=r"(r0), "=r"(r1), "=r"(r2), "=r"(r3) : "r"(a));
}
__device__ __forceinline__ void mma_bf16(float* d, const uint32_t* a, const uint32_t* b) {
    asm volatile(
        "mma.sync.aligned.m16n8k16.row.col.f32.bf16.bf16.f32 "
        "{%0,%1,%2,%3}, {%4,%5,%6,%7}, {%8,%9}, {%0,%1,%2,%3};"
        : "+f"(d[0]), "+f"(d[1]), "+f"(d[2]), "+f"(d[3])
        : "r"(a[0]), "r"(a[1]), "r"(a[2]), "r"(a[3]), "r"(b[0]), "r"(b[1]));
}

// ============================================================================
// Kernel 0: fp32 -> bf16 cast of tg_dec and tf_base (screening operands)
// ============================================================================
__global__ void cast_bf16(const float* __restrict__ A, const float* __restrict__ Bm) {
    size_t i = (size_t)blockIdx.x * blockDim.x + threadIdx.x;
    const size_t nA = (size_t)G_N * D_N;
    const size_t nB = (size_t)T_N * D_N;
    if (i < nA) {
        g_Ah[i] = __float2bfloat16(A[i]);
    } else if (i < nA + nB) {
        size_t j = i - nA;
        g_Bh[j] = __float2bfloat16(Bm[j]);
    }
}

// ============================================================================
// Kernel 1: screening GEMM (single bf16 product, HMMA) — unchanged
// ============================================================================
#define BK         32
#define AH_OFF     0
#define BH_OFF     8192
#define STG_BYTES  16384
#define NSTAGE     3
#define ALIGN_PAD  256
#define SMEM_DYN   (ALIGN_PAD + NSTAGE * STG_BYTES)
#define K_ITERS    (D_N / BK)   // 16

__device__ __forceinline__ uint32_t swz(int row, int c) {
    return (uint32_t)(row * 64 + ((c ^ ((row >> 1) & 3)) * 16));
}

__device__ __forceinline__ void load_stage(uint32_t st, int bm, int bn, int k0, int tid) {
#pragma unroll
    for (int rep = 0; rep < 2; rep++) {          // A: 128 rows x 4 chunks
        int idx = tid + rep * 256;
        int row = idx >> 2, c = idx & 3;
        int grow = bm + row;
        bool va = grow < G_N;
        size_t off = va ? ((size_t)grow * D_N + k0 + c * 8) : 0;
        cpa16(st + AH_OFF + swz(row, c), g_Ah + off, va);
    }
#pragma unroll
    for (int rep = 0; rep < 2; rep++) {          // B: 128 rows x 4 chunks
        int idx = tid + rep * 256;
        int row = idx >> 2, c = idx & 3;
        size_t off = (size_t)(bn + row) * D_N + k0 + c * 8;
        cpa16(st + BH_OFF + swz(row, c), g_Bh + off, true);
    }
}

__global__ __launch_bounds__(256) void gemm_screen() {
    extern __shared__ char sm[];
    uint32_t sb = (smem_u32(sm) + (ALIGN_PAD - 1)) & ~(uint32_t)(ALIGN_PAD - 1);
    const int tid  = threadIdx.x;
    const int wid  = tid >> 5;
    const int lane = tid & 31;
    const int wm   = wid & 3;
    const int wn   = wid >> 2;
    const int bm = blockIdx.y * 128;
    const int bn = blockIdx.x * 128;

    float acc[2][8][4];
#pragma unroll
    for (int mt = 0; mt < 2; mt++)
#pragma unroll
        for (int nt = 0; nt < 8; nt++)
#pragma unroll
            for (int r = 0; r < 4; r++) acc[mt][nt][r] = 0.f;

    load_stage(sb + 0 * STG_BYTES, bm, bn, 0, tid);  cpa_commit();
    load_stage(sb + 1 * STG_BYTES, bm, bn, 32, tid); cpa_commit();
    load_stage(sb + 2 * STG_BYTES, bm, bn, 64, tid); cpa_commit();

    const int arow = wm * 32 + (lane & 7) + ((lane >> 3) & 1) * 8;
    const int acs  = (lane >> 4);
    const int brow = wn * 64 + (lane & 7) + ((lane >> 4) << 3);
    const int bcs  = ((lane >> 3) & 1);

    for (int it = 0; it < K_ITERS; it++) {
        uint32_t st = sb + (uint32_t)(it % NSTAGE) * STG_BYTES;
        if (it < K_ITERS - 3) cpa_wait2(); else cpa_wait0();
        __syncthreads();

#pragma unroll
        for (int ks = 0; ks < 2; ks++) {
            const int c0 = ks * 2;
            uint32_t ah[2][4], bh[4][4];
#pragma unroll
            for (int mt = 0; mt < 2; mt++) {
                uint32_t ao = swz(arow + mt * 16, c0 + acs);
                ldsm_x4(ah[mt][0], ah[mt][1], ah[mt][2], ah[mt][3], st + AH_OFF + ao);
            }
#pragma unroll
            for (int np = 0; np < 4; np++) {
                uint32_t bo = swz(brow + np * 16, c0 + bcs);
                ldsm_x4(bh[np][0], bh[np][1], bh[np][2], bh[np][3], st + BH_OFF + bo);
            }
#pragma unroll
            for (int mt = 0; mt < 2; mt++)
#pragma unroll
                for (int nt = 0; nt < 8; nt++)
                    mma_bf16(acc[mt][nt], ah[mt], &bh[nt >> 1][(nt & 1) * 2]);
        }
        __syncthreads();
        if (it + 3 < K_ITERS) {
            load_stage(st, bm, bn, (it + 3) * BK, tid);
            cpa_commit();
        }
    }

    const float rs = 0.04419417382415922f;
    const int mrow = (lane >> 2);
    const int ncol = (lane & 3) * 2;
#pragma unroll
    for (int mt = 0; mt < 2; mt++) {
#pragma unroll
        for (int half = 0; half < 2; half++) {
            int m = bm + wm * 32 + mt * 16 + mrow + half * 8;
            if (m < G_N) {
                float* dst = g_sim + (size_t)m * T_N + bn + wn * 64 + ncol;
#pragma unroll
                for (int nt = 0; nt < 8; nt++) {
                    float2 v;
                    v.x = acc[mt][nt][half * 2 + 0] * rs;
                    v.y = acc[mt][nt][half * 2 + 1] * rs;
                    *(float2*)(dst + nt * 8) = v;
                }
            }
        }
    }
}

// ============================================================================
// block reductions (256 threads)
// ============================================================================
__device__ __forceinline__ float blockMax256(float v) {
    __shared__ float s[8];
#pragma unroll
    for (int o = 16; o > 0; o >>= 1)
        v = fmaxf(v, __shfl_xor_sync(0xffffffffu, v, o));
    if ((threadIdx.x & 31) == 0) s[threadIdx.x >> 5] = v;
    __syncthreads();
    float r = s[0];
#pragma unroll
    for (int i = 1; i < 8; i++) r = fmaxf(r, s[i]);
    __syncthreads();
    return r;
}
__device__ __forceinline__ float blockSum256(float v) {
    __shared__ float s[8];
#pragma unroll
    for (int o = 16; o > 0; o >>= 1)
        v += __shfl_xor_sync(0xffffffffu, v, o);
    if ((threadIdx.x & 31) == 0) s[threadIdx.x >> 5] = v;
    __syncthreads();
    float r = 0.f;
#pragma unroll
    for (int i = 0; i < 8; i++) r += s[i];
    __syncthreads();
    return r;
}

// ============================================================================
// Kernel 2a: softmax_select — unchanged from R14 (125.7 us measured).
// ============================================================================
__global__ __launch_bounds__(256) void softmax_select(const int* __restrict__ mask,
                                                      float* __restrict__ attn_out) {
    const int g    = blockIdx.x;
    const int tid  = threadIdx.x;
    const int lane = tid & 31;
    const int w    = tid >> 5;
    const float* srow = g_sim + (size_t)g * T_N;
    const int*   mrow = mask + (size_t)g * T_N;
    float* arow = attn_out + (size_t)g * T_N;

    float sv[6]; int mv[6];
#pragma unroll
    for (int i = 0; i < 6; i++) {
        int t = tid + i * 256;
        sv[i] = srow[t];
        mv[i] = mrow[t];
    }

    if (tid < K_TOP) {
        g_tkw[g * K_TOP + tid] = 0.f;
        g_tki[g * K_TOP + tid] = 0;
    }
#pragma unroll
    for (int i = 0; i < 6; i++) arow[tid + i * 256] = 0.f;

    float lm = -INFINITY;
#pragma unroll
    for (int i = 0; i < 6; i++)
        if (mv[i]) lm = fmaxf(lm, sv[i]);
    float m = blockMax256(lm);

    if (m == -INFINITY) {
        if (tid == 0) g_cnt[g] = 0;
        return;
    }

    float lsum = 0.f;
#pragma unroll
    for (int i = 0; i < 6; i++)
        if (mv[i]) lsum += expf(sv[i] - m);
    float Z = blockSum256(lsum);

    uint32_t key[6];
#pragma unroll
    for (int i = 0; i < 6; i++) {
        uint32_t u = __float_as_uint(sv[i]);
        u = (u & 0x80000000u) ? ~u : (u | 0x80000000u);
        key[i] = mv[i] ? u : 0u;
    }

    __shared__ int hist[NH][256];
    __shared__ int wtot[8];
    __shared__ int s_b1, s_ab1, s_b2, s_ab2, s_b3;
    const int hg = w >> 1;

    // pass 1
#pragma unroll
    for (int j = 0; j < NH; j++) hist[j][tid] = 0;
    __syncthreads();
#pragma unroll
    for (int i = 0; i < 6; i++) atomicAdd(&hist[hg][key[i] >> 24], 1);
    __syncthreads();
    {
        int h = hist[0][tid] + hist[1][tid] + hist[2][tid] + hist[3][tid];
        int v = h;
#pragma unroll
        for (int off = 1; off < 32; off <<= 1) {
            int o = __shfl_down_sync(0xffffffffu, v, off);
            if (lane + off < 32) v += o;
        }
        if (lane == 0) wtot[w] = v;
        __syncthreads();
        int offs = 0;
#pragma unroll
        for (int j = 0; j < 8; j++) if (j > w) offs += wtot[j];
        int suf = v + offs;
        int nxt = suf - h;
        if (suf >= NTGT && nxt < NTGT) { s_b1 = tid; s_ab1 = nxt; }
    }
    __syncthreads();
    const uint32_t b1 = (uint32_t)s_b1;
    const int ab1 = s_ab1;

    // pass 2
#pragma unroll
    for (int j = 0; j < NH; j++) hist[j][tid] = 0;
    __syncthreads();
#pragma unroll
    for (int i = 0; i < 6; i++)
        if ((key[i] >> 24) == b1) atomicAdd(&hist[hg][(key[i] >> 16) & 0xFF], 1);
    __syncthreads();
    {
        int h = hist[0][tid] + hist[1][tid] + hist[2][tid] + hist[3][tid];
        int v = h;
#pragma unroll
        for (int off = 1; off < 32; off <<= 1) {
            int o = __shfl_down_sync(0xffffffffu, v, off);
            if (lane + off < 32) v += o;
        }
        if (lane == 0) wtot[w] = v;
        __syncthreads();
        int offs = 0;
#pragma unroll
        for (int j = 0; j < 8; j++) if (j > w) offs += wtot[j];
        int suf = v + offs;
        int nxt = suf - h;
        if (ab1 + suf >= NTGT && ab1 + nxt < NTGT) { s_b2 = tid; s_ab2 = ab1 + nxt; }
    }
    __syncthreads();
    const uint32_t thr16 = (b1 << 8) | (uint32_t)s_b2;
    const int ab2 = s_ab2;

    // pass 3
#pragma unroll
    for (int j = 0; j < NH; j++) hist[j][tid] = 0;
    __syncthreads();
#pragma unroll
    for (int i = 0; i < 6; i++)
        if ((key[i] >> 16) == thr16) atomicAdd(&hist[hg][(key[i] >> 8) & 0xFF], 1);
    __syncthreads();
    {
        int h = hist[0][tid] + hist[1][tid] + hist[2][tid] + hist[3][tid];
        int v = h;
#pragma unroll
        for (int off = 1; off < 32; off <<= 1) {
            int o = __shfl_down_sync(0xffffffffu, v, off);
            if (lane + off < 32) v += o;
        }
        if (lane == 0) wtot[w] = v;
        __syncthreads();
        int offs = 0;
#pragma unroll
        for (int j = 0; j < 8; j++) if (j > w) offs += wtot[j];
        int suf = v + offs;
        int nxt = suf - h;
        if (ab2 + suf >= NTGT && ab2 + nxt < NTGT) { s_b3 = tid; }
    }
    __syncthreads();
    const uint32_t thr24 = (thr16 << 8) | (uint32_t)s_b3;

    __shared__ int s_cnt;
    if (tid == 0) s_cnt = 0;
    __syncthreads();
#pragma unroll
    for (int i = 0; i < 6; i++) {
        if (mv[i] && (key[i] >> 8) >= thr24) {
            int p = atomicAdd(&s_cnt, 1);
            if (p < CCAP) g_cand[g * CCAP + p] = tid + i * 256;
        }
    }
    __syncthreads();
    if (tid == 0) {
        g_cnt[g] = s_cnt < CCAP ? s_cnt : CCAP;
        g_mv[g] = m;
        g_Zv[g] = Z;
    }
}

// ============================================================================
// Kernel 2b: rescore_persist — PERSISTENT double-buffered rescore.
// grid=RGRID (1 block/SM), each block walks rows g = bid, bid+RGRID, ...
// Per row: prefetch next row's meta + candidate rows into the other buffer
// (cp.async group), wait current buffer, run sequential-chain rescore + rank
// on current while next stages. Chain = sequential k-ascending single FMA
// chain per candidate (order verified at 2.2e-7 across 6 runs).
//   dynamic smem: s_a[2][512] + s_rows[2][CCAP*128 float4] = 200704 B
// ============================================================================
__global__ __launch_bounds__(256) void rescore_persist(float* __restrict__ attn_out,
                                                       const float* __restrict__ tg,
                                                       const float* __restrict__ tfb) {
    extern __shared__ float dynsm[];
    float*  s_a     = dynsm;                     // [2][512]
    float4* s_rows4 = (float4*)(dynsm + 1024);   // [2][CCAP*128]

    const int tid = threadIdx.x;
    __shared__ int s_ci[2][CCAP];

    // prologue: meta + staging for the first row into buffer 0
    int g0 = blockIdx.x;
    int nc_cur = 0;
    if (g0 < G_N) {
        nc_cur = g_cnt[g0];
        if (tid < CCAP) s_ci[0][tid] = (tid < nc_cur) ? g_cand[g0 * CCAP + tid] : 0;
    }
    __syncthreads();
    if (g0 < G_N) {
        if (tid < 128)
            cpa16(smem_u32(s_a + tid * 4), tg + (size_t)g0 * D_N + tid * 4, true);
#pragma unroll
        for (int j = 0; j < (CCAP * 128) / 256; j++) {
            int lin = tid + j * 256;
            int r = lin >> 7, q = lin & 127;
            bool va = r < nc_cur;
            int c = s_ci[0][va ? r : 0];
            cpa16(smem_u32(s_rows4 + r * 128 + (q ^ (r & 7))),
                  tfb + (size_t)c * D_N + q * 4, va);
        }
    }
    cpa_commit();

    for (int g = g0; g < G_N; g += RGRID) {
        const int i  = (g - g0) / RGRID;
        const int cb = i & 1, nb = cb ^ 1;
        const int gn = g + RGRID;

        // meta for next row (safe: previous rank finished before this point
        // in program order for threads < CCAP; barrier below orders others)
        __syncthreads();
        int nc_n = 0;
        if (gn < G_N) {
            nc_n = g_cnt[gn];
            if (tid < CCAP) s_ci[nb][tid] = (tid < nc_n) ? g_cand[gn * CCAP + tid] : 0;
        }
        __syncthreads();
        // stage next row into the other buffer
        if (gn < G_N) {
            if (tid < 128)
                cpa16(smem_u32(s_a + nb * 512 + tid * 4),
                      tg + (size_t)gn * D_N + tid * 4, true);
#pragma unroll
            for (int j = 0; j < (CCAP * 128) / 256; j++) {
                int lin = tid + j * 256;
                int r = lin >> 7, q = lin & 127;
                bool va = r < nc_n;
                int c = s_ci[nb][va ? r : 0];
                cpa16(smem_u32(s_rows4 + (nb * CCAP + r) * 128 + (q ^ (r & 7))),
                      tfb + (size_t)c * D_N + q * 4, va);
            }
        }
        cpa_commit();
        cpa_wait1();        // current buffer complete; next still in flight
        __syncthreads();

        const int nC = nc_cur;
        if (nC > 0) {
            // ---- exact rescore: sequential single chain, ascending k ----
            __shared__ float s_ex[CCAP];
            if (tid < nC) {
                const float4* row = s_rows4 + (cb * CCAP + tid) * 128;
                const float*  a   = s_a + cb * 512;
                const int cx = tid & 7;
                float acc = 0.f;
#pragma unroll 4
                for (int q = 0; q < 128; q++) {
                    float4 v = row[q ^ cx];
                    const float* a4 = a + q * 4;
                    acc = fmaf(a4[0], v.x, acc);
                    acc = fmaf(a4[1], v.y, acc);
                    acc = fmaf(a4[2], v.z, acc);
                    acc = fmaf(a4[3], v.w, acc);
                }
                s_ex[tid] = acc / 22.627416997969522f;
            }
            __syncthreads();

            // ---- exact rank: (value desc, index asc) ----
            __shared__ int   s_rank[CCAP];
            __shared__ float s_x[CCAP];
            __shared__ float s_mex, s_S;
            if (tid < CCAP) {
                s_x[tid] = 0.f;
                if (tid < nC) {
                    float exi = s_ex[tid]; int ci = s_ci[cb][tid];
                    int rank = 0;
                    for (int j = 0; j < nC; j++) {
                        float exj = s_ex[j];
                        if (exj > exi || (exj == exi && s_ci[cb][j] < ci)) rank++;
                    }
                    s_rank[tid] = rank;
                    if (rank == 0) s_mex = exi;
                }
            }
            __syncthreads();

            const float m = g_mv[g];
            const float Z = g_Zv[g];
            const float mex = s_mex;
            const float Zp = Z * expf(m - mex);
            if (tid < nC && s_rank[tid] < K_TOP)
                s_x[tid] = expf(s_ex[tid] - mex) / Zp;   // ref: a = e/Z
            __syncthreads();
            if (tid == 0) {
                float S = 0.f;
#pragma unroll
                for (int j = 0; j < CCAP; j++) S += s_x[j];
                s_S = S;
            }
            __syncthreads();

            const float den = s_S + 1e-8f;    // ref: attn / (sum + 1e-8)
            if (tid < nC && s_rank[tid] < K_TOP) {
                float outx = s_x[tid] / den;
                int c = s_ci[cb][tid];
                attn_out[(size_t)g * T_N + c] = outx;   // row pre-zeroed
                g_tki[g * K_TOP + s_rank[tid]] = c;
                g_tkw[g * K_TOP + s_rank[tid]] = outx;
            }
        }
        nc_cur = nc_n;
    }
}

// ============================================================================
// Kernel 3a: transpose tf_expr [B,T] -> g_tfT [T,B]
// ============================================================================
__global__ void transpose_tf(const float* __restrict__ tf) {
    __shared__ float tile[32][33];
    int bx = blockIdx.x * 32;
    int by = blockIdx.y * 32;
#pragma unroll
    for (int r = 0; r < 32; r += 8)
        tile[threadIdx.y + r][threadIdx.x] =
            tf[(size_t)(by + threadIdx.y + r) * T_N + bx + threadIdx.x];
    __syncthreads();
#pragma unroll
    for (int r = 0; r < 32; r += 8)
        g_tfT[(size_t)(bx + threadIdx.y + r) * B_N + by + threadIdx.x] =
            tile[threadIdx.x][threadIdx.y + r];
}

// ============================================================================
// Kernel 3b: sparse combine  out[b,g] = scale * sum_j w[g,j]*tfT[idx[g,j], b]
// ============================================================================
__global__ __launch_bounds__(256) void combine(const float* __restrict__ scale,
                                               float* __restrict__ outS) {
    const int g0 = blockIdx.x * 8;
    const int b  = threadIdx.x;
    __shared__ int   si[8][K_TOP];
    __shared__ float sw[8][K_TOP];
    {
        int q = threadIdx.x >> 5, j = threadIdx.x & 31;
        si[q][j] = g_tki[(g0 + q) * K_TOP + j];
        sw[q][j] = g_tkw[(g0 + q) * K_TOP + j];
    }
    __syncthreads();

    float acc[8];
#pragma unroll
    for (int q = 0; q < 8; q++) acc[q] = 0.f;

#pragma unroll 4
    for (int j = 0; j < K_TOP; j++) {
#pragma unroll
        for (int q = 0; q < 8; q++)
            acc[q] = fmaf(sw[q][j], g_tfT[si[q][j] * B_N + b], acc[q]);
    }

    float sc = scale[0];
    float4 o0 = make_float4(sc * acc[0], sc * acc[1], sc * acc[2], sc * acc[3]);
    float4 o1 = make_float4(sc * acc[4], sc * acc[5], sc * acc[6], sc * acc[7]);
    float* dst = outS + (size_t)b * G_N + g0;
    *(float4*)dst = o0;
    *(float4*)(dst + 4) = o1;
}

// ============================================================================
// launch
// ============================================================================
extern "C" void kernel_launch(void* const* d_in, const int* in_sizes, int n_in,
                              void* d_out, int out_size) {
    const float* tg_dec     = (const float*)d_in[0];
    const float* tf_base    = (const float*)d_in[1];
    const float* tf_expr    = (const float*)d_in[2];
    const int*   motif_mask = (const int*)d_in[3];
    const float* scale      = (const float*)d_in[4];

    float* out        = (float*)d_out;
    float* out_scalar = out;                          // [B, G]
    float* out_attn   = out + (size_t)B_N * G_N;      // [G, T]

    const int resc_dyn = (1024 + 2 * CCAP * 512) * (int)sizeof(float);  // 200704 B

    cudaFuncSetAttribute(gemm_screen,
                         cudaFuncAttributeMaxDynamicSharedMemorySize, SMEM_DYN);
    cudaFuncSetAttribute(rescore_persist,
                         cudaFuncAttributeMaxDynamicSharedMemorySize, resc_dyn);

    // bf16 cast of screening operands
    {
        size_t total = (size_t)G_N * D_N + (size_t)T_N * D_N;
        int blocks = (int)((total + 255) / 256);
        cast_bf16<<<blocks, 256>>>(tg_dec, tf_base);
    }
    // transpose tf_expr (independent; needed by combine)
    {
        dim3 blk(32, 8), grd(T_N / 32, B_N / 32);
        transpose_tf<<<grd, blk>>>(tf_expr);
    }
    // screening GEMM (single bf16 HMMA product)
    {
        dim3 grd(T_N / 128, (G_N + 127) / 128);   // (12, 157)
        gemm_screen<<<grd, 256, SMEM_DYN>>>();
    }
    // high-occupancy softmax + radix select + dense zeroing
    softmax_select<<<G_N, 256>>>(motif_mask, out_attn);
    // persistent double-buffered exact rescore + scatter
    rescore_persist<<<RGRID, 256, resc_dyn>>>(out_attn, tg_dec, tf_base);
    // sparse weighted combine
    combine<<<G_N / 8, 256>>>(scale, out_scalar);
}

// round 16
// speedup vs baseline: 1.1943x; 1.1943x over previous
#include <cuda_runtime.h>
#include <cuda_bf16.h>
#include <math.h>
#include <stdint.h>
#include <cstdint>

#define G_N   20000
#define T_N   1536
#define D_N   512
#define B_N   256
#define K_TOP 32
#define NTGT  44      // radix-select target rank (Gamma(12) gap margin over 32)
#define CCAP  48      // candidate capacity; 24-bit threshold => collected ~ NTGT+0
#define NH    4       // histogram copies (warp pairs)
#define RGRID 148     // persistent rescore blocks (1 per SM)

// ---------------- device scratch (static: no allocation at runtime) ----------------
__device__ float          g_sim[(size_t)G_N * T_N];   // [G, T] screening similarity
__device__ float          g_tfT[T_N * B_N];           // tf_expr transposed [T, B]
__device__ int            g_tki[G_N * K_TOP];
__device__ float          g_tkw[G_N * K_TOP];
__device__ __nv_bfloat16  g_Ah[(size_t)G_N * D_N];    // tg_dec bf16
__device__ __nv_bfloat16  g_Bh[(size_t)T_N * D_N];    // tf_base bf16
__device__ int            g_cand[G_N * CCAP];         // per-row candidate indices
__device__ int            g_cnt[G_N];                 // per-row candidate count
__device__ float          g_mv[G_N];                  // per-row approx max
__device__ float          g_Zv[G_N];                  // per-row approx Z

// ============================================================================
// PTX helpers (baseline PTX only — harness ptxas targets plain sm_103;
// tcgen05 is rejected there, mma.sync/cp.async/ldmatrix are sm_80+ baseline)
// ============================================================================
__device__ __forceinline__ uint32_t smem_u32(const void* p) {
    uint32_t a;
    asm("{ .reg .u64 t; cvta.to.shared.u64 t, %1; cvt.u32.u64 %0, t; }"
        : "=r"(a) : "l"(p));
    return a;
}
__device__ __forceinline__ void cpa16(uint32_t d, const void* s, bool v) {
    int sz = v ? 16 : 0;
    asm volatile("cp.async.cg.shared.global [%0], [%1], 16, %2;"
                 :: "r"(d), "l"(s), "r"(sz));
}
__device__ __forceinline__ void cpa_commit() {
    asm volatile("cp.async.commit_group;" ::: "memory");
}
__device__ __forceinline__ void cpa_wait2() {
    asm volatile("cp.async.wait_group 2;" ::: "memory");
}
__device__ __forceinline__ void cpa_wait0() {
    asm volatile("cp.async.wait_group 0;" ::: "memory");
}
__device__ __forceinline__ void bar_stage() {   // warps 0-5 (192 threads)
    asm volatile("bar.sync 1, 192;" ::: "memory");
}
__device__ __forceinline__ void bar_chain() {   // warps 6-7 (64 threads)
    asm volatile("bar.sync 2, 64;" ::: "memory");
}
__device__ __forceinline__ void ldsm_x4(uint32_t& r0, uint32_t& r1,
                                        uint32_t& r2, uint32_t& r3, uint32_t a) {
    asm volatile("ldmatrix.sync.aligned.m8n8.x4.shared.b16 {%0,%1,%2,%3}, [%4];"
                 : "=r"(r0), "=r"(r1), "=r"(r2), "=r"(r3) : "r"(a));
}
__device__ __forceinline__ void mma_bf16(float* d, const uint32_t* a, const uint32_t* b) {
    asm volatile(
        "mma.sync.aligned.m16n8k16.row.col.f32.bf16.bf16.f32 "
        "{%0,%1,%2,%3}, {%4,%5,%6,%7}, {%8,%9}, {%0,%1,%2,%3};"
        : "+f"(d[0]), "+f"(d[1]), "+f"(d[2]), "+f"(d[3])
        : "r"(a[0]), "r"(a[1]), "r"(a[2]), "r"(a[3]), "r"(b[0]), "r"(b[1]));
}

// ============================================================================
// Kernel 0: fp32 -> bf16 cast of tg_dec and tf_base (screening operands)
// ============================================================================
__global__ void cast_bf16(const float* __restrict__ A, const float* __restrict__ Bm) {
    size_t i = (size_t)blockIdx.x * blockDim.x + threadIdx.x;
    const size_t nA = (size_t)G_N * D_N;
    const size_t nB = (size_t)T_N * D_N;
    if (i < nA) {
        g_Ah[i] = __float2bfloat16(A[i]);
    } else if (i < nA + nB) {
        size_t j = i - nA;
        g_Bh[j] = __float2bfloat16(Bm[j]);
    }
}

// ============================================================================
// Kernel 1: screening GEMM (single bf16 product, HMMA) — unchanged
// ============================================================================
#define BK         32
#define AH_OFF     0
#define BH_OFF     8192
#define STG_BYTES  16384
#define NSTAGE     3
#define ALIGN_PAD  256
#define SMEM_DYN   (ALIGN_PAD + NSTAGE * STG_BYTES)
#define K_ITERS    (D_N / BK)   // 16

__device__ __forceinline__ uint32_t swz(int row, int c) {
    return (uint32_t)(row * 64 + ((c ^ ((row >> 1) & 3)) * 16));
}

__device__ __forceinline__ void load_stage(uint32_t st, int bm, int bn, int k0, int tid) {
#pragma unroll
    for (int rep = 0; rep < 2; rep++) {          // A: 128 rows x 4 chunks
        int idx = tid + rep * 256;
        int row = idx >> 2, c = idx & 3;
        int grow = bm + row;
        bool va = grow < G_N;
        size_t off = va ? ((size_t)grow * D_N + k0 + c * 8) : 0;
        cpa16(st + AH_OFF + swz(row, c), g_Ah + off, va);
    }
#pragma unroll
    for (int rep = 0; rep < 2; rep++) {          // B: 128 rows x 4 chunks
        int idx = tid + rep * 256;
        int row = idx >> 2, c = idx & 3;
        size_t off = (size_t)(bn + row) * D_N + k0 + c * 8;
        cpa16(st + BH_OFF + swz(row, c), g_Bh + off, true);
    }
}

__global__ __launch_bounds__(256) void gemm_screen() {
    extern __shared__ char sm[];
    uint32_t sb = (smem_u32(sm) + (ALIGN_PAD - 1)) & ~(uint32_t)(ALIGN_PAD - 1);
    const int tid  = threadIdx.x;
    const int wid  = tid >> 5;
    const int lane = tid & 31;
    const int wm   = wid & 3;
    const int wn   = wid >> 2;
    const int bm = blockIdx.y * 128;
    const int bn = blockIdx.x * 128;

    float acc[2][8][4];
#pragma unroll
    for (int mt = 0; mt < 2; mt++)
#pragma unroll
        for (int nt = 0; nt < 8; nt++)
#pragma unroll
            for (int r = 0; r < 4; r++) acc[mt][nt][r] = 0.f;

    load_stage(sb + 0 * STG_BYTES, bm, bn, 0, tid);  cpa_commit();
    load_stage(sb + 1 * STG_BYTES, bm, bn, 32, tid); cpa_commit();
    load_stage(sb + 2 * STG_BYTES, bm, bn, 64, tid); cpa_commit();

    const int arow = wm * 32 + (lane & 7) + ((lane >> 3) & 1) * 8;
    const int acs  = (lane >> 4);
    const int brow = wn * 64 + (lane & 7) + ((lane >> 4) << 3);
    const int bcs  = ((lane >> 3) & 1);

    for (int it = 0; it < K_ITERS; it++) {
        uint32_t st = sb + (uint32_t)(it % NSTAGE) * STG_BYTES;
        if (it < K_ITERS - 3) cpa_wait2(); else cpa_wait0();
        __syncthreads();

#pragma unroll
        for (int ks = 0; ks < 2; ks++) {
            const int c0 = ks * 2;
            uint32_t ah[2][4], bh[4][4];
#pragma unroll
            for (int mt = 0; mt < 2; mt++) {
                uint32_t ao = swz(arow + mt * 16, c0 + acs);
                ldsm_x4(ah[mt][0], ah[mt][1], ah[mt][2], ah[mt][3], st + AH_OFF + ao);
            }
#pragma unroll
            for (int np = 0; np < 4; np++) {
                uint32_t bo = swz(brow + np * 16, c0 + bcs);
                ldsm_x4(bh[np][0], bh[np][1], bh[np][2], bh[np][3], st + BH_OFF + bo);
            }
#pragma unroll
            for (int mt = 0; mt < 2; mt++)
#pragma unroll
                for (int nt = 0; nt < 8; nt++)
                    mma_bf16(acc[mt][nt], ah[mt], &bh[nt >> 1][(nt & 1) * 2]);
        }
        __syncthreads();
        if (it + 3 < K_ITERS) {
            load_stage(st, bm, bn, (it + 3) * BK, tid);
            cpa_commit();
        }
    }

    const float rs = 0.04419417382415922f;
    const int mrow = (lane >> 2);
    const int ncol = (lane & 3) * 2;
#pragma unroll
    for (int mt = 0; mt < 2; mt++) {
#pragma unroll
        for (int half = 0; half < 2; half++) {
            int m = bm + wm * 32 + mt * 16 + mrow + half * 8;
            if (m < G_N) {
                float* dst = g_sim + (size_t)m * T_N + bn + wn * 64 + ncol;
#pragma unroll
                for (int nt = 0; nt < 8; nt++) {
                    float2 v;
                    v.x = acc[mt][nt][half * 2 + 0] * rs;
                    v.y = acc[mt][nt][half * 2 + 1] * rs;
                    *(float2*)(dst + nt * 8) = v;
                }
            }
        }
    }
}

// ============================================================================
// block reductions (256 threads)
// ============================================================================
__device__ __forceinline__ float blockMax256(float v) {
    __shared__ float s[8];
#pragma unroll
    for (int o = 16; o > 0; o >>= 1)
        v = fmaxf(v, __shfl_xor_sync(0xffffffffu, v, o));
    if ((threadIdx.x & 31) == 0) s[threadIdx.x >> 5] = v;
    __syncthreads();
    float r = s[0];
#pragma unroll
    for (int i = 1; i < 8; i++) r = fmaxf(r, s[i]);
    __syncthreads();
    return r;
}
__device__ __forceinline__ float blockSum256(float v) {
    __shared__ float s[8];
#pragma unroll
    for (int o = 16; o > 0; o >>= 1)
        v += __shfl_xor_sync(0xffffffffu, v, o);
    if ((threadIdx.x & 31) == 0) s[threadIdx.x >> 5] = v;
    __syncthreads();
    float r = 0.f;
#pragma unroll
    for (int i = 0; i < 8; i++) r += s[i];
    __syncthreads();
    return r;
}

// ============================================================================
// Kernel 2a: softmax_select — unchanged (126 us measured in R14/R15).
// ============================================================================
__global__ __launch_bounds__(256) void softmax_select(const int* __restrict__ mask,
                                                      float* __restrict__ attn_out) {
    const int g    = blockIdx.x;
    const int tid  = threadIdx.x;
    const int lane = tid & 31;
    const int w    = tid >> 5;
    const float* srow = g_sim + (size_t)g * T_N;
    const int*   mrow = mask + (size_t)g * T_N;
    float* arow = attn_out + (size_t)g * T_N;

    float sv[6]; int mv[6];
#pragma unroll
    for (int i = 0; i < 6; i++) {
        int t = tid + i * 256;
        sv[i] = srow[t];
        mv[i] = mrow[t];
    }

    if (tid < K_TOP) {
        g_tkw[g * K_TOP + tid] = 0.f;
        g_tki[g * K_TOP + tid] = 0;
    }
#pragma unroll
    for (int i = 0; i < 6; i++) arow[tid + i * 256] = 0.f;

    float lm = -INFINITY;
#pragma unroll
    for (int i = 0; i < 6; i++)
        if (mv[i]) lm = fmaxf(lm, sv[i]);
    float m = blockMax256(lm);

    if (m == -INFINITY) {
        if (tid == 0) g_cnt[g] = 0;
        return;
    }

    float lsum = 0.f;
#pragma unroll
    for (int i = 0; i < 6; i++)
        if (mv[i]) lsum += expf(sv[i] - m);
    float Z = blockSum256(lsum);

    uint32_t key[6];
#pragma unroll
    for (int i = 0; i < 6; i++) {
        uint32_t u = __float_as_uint(sv[i]);
        u = (u & 0x80000000u) ? ~u : (u | 0x80000000u);
        key[i] = mv[i] ? u : 0u;
    }

    __shared__ int hist[NH][256];
    __shared__ int wtot[8];
    __shared__ int s_b1, s_ab1, s_b2, s_ab2, s_b3;
    const int hg = w >> 1;

    // pass 1
#pragma unroll
    for (int j = 0; j < NH; j++) hist[j][tid] = 0;
    __syncthreads();
#pragma unroll
    for (int i = 0; i < 6; i++) atomicAdd(&hist[hg][key[i] >> 24], 1);
    __syncthreads();
    {
        int h = hist[0][tid] + hist[1][tid] + hist[2][tid] + hist[3][tid];
        int v = h;
#pragma unroll
        for (int off = 1; off < 32; off <<= 1) {
            int o = __shfl_down_sync(0xffffffffu, v, off);
            if (lane + off < 32) v += o;
        }
        if (lane == 0) wtot[w] = v;
        __syncthreads();
        int offs = 0;
#pragma unroll
        for (int j = 0; j < 8; j++) if (j > w) offs += wtot[j];
        int suf = v + offs;
        int nxt = suf - h;
        if (suf >= NTGT && nxt < NTGT) { s_b1 = tid; s_ab1 = nxt; }
    }
    __syncthreads();
    const uint32_t b1 = (uint32_t)s_b1;
    const int ab1 = s_ab1;

    // pass 2
#pragma unroll
    for (int j = 0; j < NH; j++) hist[j][tid] = 0;
    __syncthreads();
#pragma unroll
    for (int i = 0; i < 6; i++)
        if ((key[i] >> 24) == b1) atomicAdd(&hist[hg][(key[i] >> 16) & 0xFF], 1);
    __syncthreads();
    {
        int h = hist[0][tid] + hist[1][tid] + hist[2][tid] + hist[3][tid];
        int v = h;
#pragma unroll
        for (int off = 1; off < 32; off <<= 1) {
            int o = __shfl_down_sync(0xffffffffu, v, off);
            if (lane + off < 32) v += o;
        }
        if (lane == 0) wtot[w] = v;
        __syncthreads();
        int offs = 0;
#pragma unroll
        for (int j = 0; j < 8; j++) if (j > w) offs += wtot[j];
        int suf = v + offs;
        int nxt = suf - h;
        if (ab1 + suf >= NTGT && ab1 + nxt < NTGT) { s_b2 = tid; s_ab2 = ab1 + nxt; }
    }
    __syncthreads();
    const uint32_t thr16 = (b1 << 8) | (uint32_t)s_b2;
    const int ab2 = s_ab2;

    // pass 3
#pragma unroll
    for (int j = 0; j < NH; j++) hist[j][tid] = 0;
    __syncthreads();
#pragma unroll
    for (int i = 0; i < 6; i++)
        if ((key[i] >> 16) == thr16) atomicAdd(&hist[hg][(key[i] >> 8) & 0xFF], 1);
    __syncthreads();
    {
        int h = hist[0][tid] + hist[1][tid] + hist[2][tid] + hist[3][tid];
        int v = h;
#pragma unroll
        for (int off = 1; off < 32; off <<= 1) {
            int o = __shfl_down_sync(0xffffffffu, v, off);
            if (lane + off < 32) v += o;
        }
        if (lane == 0) wtot[w] = v;
        __syncthreads();
        int offs = 0;
#pragma unroll
        for (int j = 0; j < 8; j++) if (j > w) offs += wtot[j];
        int suf = v + offs;
        int nxt = suf - h;
        if (ab2 + suf >= NTGT && ab2 + nxt < NTGT) { s_b3 = tid; }
    }
    __syncthreads();
    const uint32_t thr24 = (thr16 << 8) | (uint32_t)s_b3;

    __shared__ int s_cnt;
    if (tid == 0) s_cnt = 0;
    __syncthreads();
#pragma unroll
    for (int i = 0; i < 6; i++) {
        if (mv[i] && (key[i] >> 8) >= thr24) {
            int p = atomicAdd(&s_cnt, 1);
            if (p < CCAP) g_cand[g * CCAP + p] = tid + i * 256;
        }
    }
    __syncthreads();
    if (tid == 0) {
        g_cnt[g] = s_cnt < CCAP ? s_cnt : CCAP;
        g_mv[g] = m;
        g_Zv[g] = Z;
    }
}

// ============================================================================
// Kernel 2b: rescore_ws — persistent, WARP-SPECIALIZED producer/consumer.
// grid=RGRID (1 block/SM); warps 0-5 stage row i+1 (meta LDG -> named barrier
// -> 16B swizzled cp.async -> wait_group 0) WHILE warps 6-7 compute row i
// (sequential k-ascending single-FMA chains — the order verified at 2.19e-7
// seven times — then exact rank + scatter, phases via bar.sync 2,64).
// One __syncthreads per row swaps buffers.
//   dynamic smem: s_a[2][512] + s_rows[2][CCAP*128 float4] = 200704 B
// ============================================================================
__global__ __launch_bounds__(256) void rescore_ws(float* __restrict__ attn_out,
                                                  const float* __restrict__ tg,
                                                  const float* __restrict__ tfb) {
    extern __shared__ float dynsm[];
    float*  s_a     = dynsm;                     // [2][512]
    float4* s_rows4 = (float4*)(dynsm + 1024);   // [2][CCAP*128]

    __shared__ int   s_ci[2][CCAP];
    __shared__ int   s_nc[2];
    __shared__ float s_ex[CCAP];
    __shared__ int   s_rank[CCAP];
    __shared__ float s_x[CCAP];
    __shared__ float s_mex, s_S;

    const int tid = threadIdx.x;
    const bool is_stage = (tid < 192);
    const int g0 = blockIdx.x;

    // ---- prologue: stage warps fill buffer 0 with row g0 ----
    if (is_stage) {
        if (tid == 0) s_nc[0] = g_cnt[g0];
        if (tid < CCAP) s_ci[0][tid] = g_cand[g0 * CCAP + tid];
        bar_stage();
        const int nc0 = s_nc[0];
        if (tid < 128)
            cpa16(smem_u32(s_a + tid * 4), tg + (size_t)g0 * D_N + tid * 4, true);
#pragma unroll
        for (int j = 0; j < (CCAP * 128) / 192; j++) {   // 32 per thread
            int lin = tid + j * 192;
            int r = lin >> 7, q = lin & 127;
            bool va = r < nc0;
            int c = s_ci[0][r];
            cpa16(smem_u32(s_rows4 + r * 128 + (q ^ (r & 7))),
                  tfb + (size_t)(va ? c : 0) * D_N + q * 4, va);
        }
        cpa_commit();
        cpa_wait0();
    }
    __syncthreads();

    int iter = 0;
    for (int g = g0; g < G_N; g += RGRID, iter++) {
        const int cb = iter & 1, nb = cb ^ 1;
        const int gn = g + RGRID;

        if (is_stage) {
            // ---------- producer: stage row gn into buffer nb ----------
            if (gn < G_N) {
                if (tid == 0) s_nc[nb] = g_cnt[gn];
                if (tid < CCAP) s_ci[nb][tid] = g_cand[gn * CCAP + tid];
                bar_stage();
                const int nc_n = s_nc[nb];
                if (tid < 128)
                    cpa16(smem_u32(s_a + nb * 512 + tid * 4),
                          tg + (size_t)gn * D_N + tid * 4, true);
#pragma unroll
                for (int j = 0; j < (CCAP * 128) / 192; j++) {
                    int lin = tid + j * 192;
                    int r = lin >> 7, q = lin & 127;
                    bool va = r < nc_n;
                    int c = s_ci[nb][r];
                    cpa16(smem_u32(s_rows4 + (nb * CCAP + r) * 128 + (q ^ (r & 7))),
                          tfb + (size_t)(va ? c : 0) * D_N + q * 4, va);
                }
                cpa_commit();
                cpa_wait0();
            }
        } else {
            // ---------- consumer: compute row g from buffer cb ----------
            const int ct = tid - 192;            // 0..63
            const int nC = s_nc[cb];
            if (nC > 0) {
                const float m = g_mv[g];         // issued early, used late
                const float Z = g_Zv[g];

                if (ct < nC) {                   // sequential single chain
                    const float4* row = s_rows4 + (size_t)(cb * CCAP + ct) * 128;
                    const float*  a   = s_a + cb * 512;
                    const int cx = ct & 7;
                    float acc = 0.f;
#pragma unroll 4
                    for (int q = 0; q < 128; q++) {
                        float4 v = row[q ^ cx];
                        const float* a4 = a + q * 4;
                        acc = fmaf(a4[0], v.x, acc);
                        acc = fmaf(a4[1], v.y, acc);
                        acc = fmaf(a4[2], v.z, acc);
                        acc = fmaf(a4[3], v.w, acc);
                    }
                    s_ex[ct] = acc / 22.627416997969522f;
                }
                bar_chain();

                if (ct < CCAP) {                 // exact rank (value desc, idx asc)
                    s_x[ct] = 0.f;
                    if (ct < nC) {
                        float exi = s_ex[ct]; int ci = s_ci[cb][ct];
                        int rank = 0;
                        for (int j = 0; j < nC; j++) {
                            float exj = s_ex[j];
                            if (exj > exi || (exj == exi && s_ci[cb][j] < ci)) rank++;
                        }
                        s_rank[ct] = rank;
                        if (rank == 0) s_mex = exi;
                    }
                }
                bar_chain();

                const float mex = s_mex;
                const float Zp = Z * expf(m - mex);   // Z re-referenced to exact max
                if (ct < nC && s_rank[ct] < K_TOP)
                    s_x[ct] = expf(s_ex[ct] - mex) / Zp;   // ref: a = e/Z
                bar_chain();
                if (ct == 0) {
                    float S = 0.f;
#pragma unroll
                    for (int j = 0; j < CCAP; j++) S += s_x[j];
                    s_S = S;
                }
                bar_chain();

                const float den = s_S + 1e-8f;    // ref: attn / (sum + 1e-8)
                if (ct < nC && s_rank[ct] < K_TOP) {
                    float outx = s_x[ct] / den;
                    int c = s_ci[cb][ct];
                    attn_out[(size_t)g * T_N + c] = outx;   // row pre-zeroed
                    g_tki[g * K_TOP + s_rank[ct]] = c;
                    g_tkw[g * K_TOP + s_rank[ct]] = outx;
                }
            }
        }
        __syncthreads();   // swap buffers; staged data visible to consumers
    }
}

// ============================================================================
// Kernel 3a: transpose tf_expr [B,T] -> g_tfT [T,B]
// ============================================================================
__global__ void transpose_tf(const float* __restrict__ tf) {
    __shared__ float tile[32][33];
    int bx = blockIdx.x * 32;
    int by = blockIdx.y * 32;
#pragma unroll
    for (int r = 0; r < 32; r += 8)
        tile[threadIdx.y + r][threadIdx.x] =
            tf[(size_t)(by + threadIdx.y + r) * T_N + bx + threadIdx.x];
    __syncthreads();
#pragma unroll
    for (int r = 0; r < 32; r += 8)
        g_tfT[(size_t)(bx + threadIdx.y + r) * B_N + by + threadIdx.x] =
            tile[threadIdx.x][threadIdx.y + r];
}

// ============================================================================
// Kernel 3b: sparse combine  out[b,g] = scale * sum_j w[g,j]*tfT[idx[g,j], b]
// ============================================================================
__global__ __launch_bounds__(256) void combine(const float* __restrict__ scale,
                                               float* __restrict__ outS) {
    const int g0 = blockIdx.x * 8;
    const int b  = threadIdx.x;
    __shared__ int   si[8][K_TOP];
    __shared__ float sw[8][K_TOP];
    {
        int q = threadIdx.x >> 5, j = threadIdx.x & 31;
        si[q][j] = g_tki[(g0 + q) * K_TOP + j];
        sw[q][j] = g_tkw[(g0 + q) * K_TOP + j];
    }
    __syncthreads();

    float acc[8];
#pragma unroll
    for (int q = 0; q < 8; q++) acc[q] = 0.f;

#pragma unroll 4
    for (int j = 0; j < K_TOP; j++) {
#pragma unroll
        for (int q = 0; q < 8; q++)
            acc[q] = fmaf(sw[q][j], g_tfT[si[q][j] * B_N + b], acc[q]);
    }

    float sc = scale[0];
    float4 o0 = make_float4(sc * acc[0], sc * acc[1], sc * acc[2], sc * acc[3]);
    float4 o1 = make_float4(sc * acc[4], sc * acc[5], sc * acc[6], sc * acc[7]);
    float* dst = outS + (size_t)b * G_N + g0;
    *(float4*)dst = o0;
    *(float4*)(dst + 4) = o1;
}

// ============================================================================
// launch
// ============================================================================
extern "C" void kernel_launch(void* const* d_in, const int* in_sizes, int n_in,
                              void* d_out, int out_size) {
    const float* tg_dec     = (const float*)d_in[0];
    const float* tf_base    = (const float*)d_in[1];
    const float* tf_expr    = (const float*)d_in[2];
    const int*   motif_mask = (const int*)d_in[3];
    const float* scale      = (const float*)d_in[4];

    float* out        = (float*)d_out;
    float* out_scalar = out;                          // [B, G]
    float* out_attn   = out + (size_t)B_N * G_N;      // [G, T]

    const int resc_dyn = (1024 + 2 * CCAP * 512) * (int)sizeof(float);  // 200704 B

    cudaFuncSetAttribute(gemm_screen,
                         cudaFuncAttributeMaxDynamicSharedMemorySize, SMEM_DYN);
    cudaFuncSetAttribute(rescore_ws,
                         cudaFuncAttributeMaxDynamicSharedMemorySize, resc_dyn);

    // bf16 cast of screening operands
    {
        size_t total = (size_t)G_N * D_N + (size_t)T_N * D_N;
        int blocks = (int)((total + 255) / 256);
        cast_bf16<<<blocks, 256>>>(tg_dec, tf_base);
    }
    // transpose tf_expr (independent; needed by combine)
    {
        dim3 blk(32, 8), grd(T_N / 32, B_N / 32);
        transpose_tf<<<grd, blk>>>(tf_expr);
    }
    // screening GEMM (single bf16 HMMA product)
    {
        dim3 grd(T_N / 128, (G_N + 127) / 128);   // (12, 157)
        gemm_screen<<<grd, 256, SMEM_DYN>>>();
    }
    // high-occupancy softmax + radix select + dense zeroing
    softmax_select<<<G_N, 256>>>(motif_mask, out_attn);
    // persistent warp-specialized exact rescore + scatter
    rescore_ws<<<RGRID, 256, resc_dyn>>>(out_attn, tg_dec, tf_base);
    // sparse weighted combine
    combine<<<G_N / 8, 256>>>(scale, out_scalar);
}

// round 17
// speedup vs baseline: 2.0194x; 1.6908x over previous
#include <cuda_runtime.h>
#include <cuda_bf16.h>
#include <math.h>
#include <stdint.h>
#include <cstdint>

#define G_N   20000
#define T_N   1536
#define D_N   512
#define B_N   256
#define K_TOP 32
#define NTGT  44      // radix-select target rank (Gamma(12) gap margin over 32)
#define CCAP  48      // candidate capacity; 24-bit threshold => collected ~ NTGT+0
#define NH    4       // histogram copies (warp pairs)

// ---------------- device scratch (static: no allocation at runtime) ----------------
__device__ float          g_sim[(size_t)G_N * T_N];   // [G, T] screening similarity
__device__ float          g_tfT[T_N * B_N];           // tf_expr transposed [T, B]
__device__ int            g_tki[G_N * K_TOP];
__device__ float          g_tkw[G_N * K_TOP];
__device__ __nv_bfloat16  g_Ah[(size_t)G_N * D_N];    // tg_dec bf16
__device__ __nv_bfloat16  g_Bh[(size_t)T_N * D_N];    // tf_base bf16
__device__ int            g_cand[G_N * CCAP];         // per-row candidate indices
__device__ int            g_cnt[G_N];                 // per-row candidate count
__device__ float          g_mv[G_N];                  // per-row approx max
__device__ float          g_Zv[G_N];                  // per-row approx Z

// ============================================================================
// PTX helpers (baseline PTX only — harness ptxas targets plain sm_103;
// tcgen05 is rejected there, mma.sync/cp.async/ldmatrix are sm_80+ baseline)
// ============================================================================
__device__ __forceinline__ uint32_t smem_u32(const void* p) {
    uint32_t a;
    asm("{ .reg .u64 t; cvta.to.shared.u64 t, %1; cvt.u32.u64 %0, t; }"
        : "=r"(a) : "l"(p));
    return a;
}
__device__ __forceinline__ void cpa16(uint32_t d, const void* s, bool v) {
    int sz = v ? 16 : 0;
    asm volatile("cp.async.cg.shared.global [%0], [%1], 16, %2;"
                 :: "r"(d), "l"(s), "r"(sz));
}
__device__ __forceinline__ void cpa_commit() {
    asm volatile("cp.async.commit_group;" ::: "memory");
}
__device__ __forceinline__ void cpa_wait2() {
    asm volatile("cp.async.wait_group 2;" ::: "memory");
}
__device__ __forceinline__ void cpa_wait0() {
    asm volatile("cp.async.wait_group 0;" ::: "memory");
}
__device__ __forceinline__ void ldsm_x4(uint32_t& r0, uint32_t& r1,
                                        uint32_t& r2, uint32_t& r3, uint32_t a) {
    asm volatile("ldmatrix.sync.aligned.m8n8.x4.shared.b16 {%0,%1,%2,%3}, [%4];"
                 : "=r"(r0), "=r"(r1), "=r"(r2), "=r"(r3) : "r"(a));
}
__device__ __forceinline__ void mma_bf16(float* d, const uint32_t* a, const uint32_t* b) {
    asm volatile(
        "mma.sync.aligned.m16n8k16.row.col.f32.bf16.bf16.f32 "
        "{%0,%1,%2,%3}, {%4,%5,%6,%7}, {%8,%9}, {%0,%1,%2,%3};"
        : "+f"(d[0]), "+f"(d[1]), "+f"(d[2]), "+f"(d[3])
        : "r"(a[0]), "r"(a[1]), "r"(a[2]), "r"(a[3]), "r"(b[0]), "r"(b[1]));
}

// ============================================================================
// Kernel 0: fp32 -> bf16 cast of tg_dec and tf_base (screening operands)
// ============================================================================
__global__ void cast_bf16(const float* __restrict__ A, const float* __restrict__ Bm) {
    size_t i = (size_t)blockIdx.x * blockDim.x + threadIdx.x;
    const size_t nA = (size_t)G_N * D_N;
    const size_t nB = (size_t)T_N * D_N;
    if (i < nA) {
        g_Ah[i] = __float2bfloat16(A[i]);
    } else if (i < nA + nB) {
        size_t j = i - nA;
        g_Bh[j] = __float2bfloat16(Bm[j]);
    }
}

// ============================================================================
// Kernel 1: screening GEMM (single bf16 product, HMMA) — unchanged
// ============================================================================
#define BK         32
#define AH_OFF     0
#define BH_OFF     8192
#define STG_BYTES  16384
#define NSTAGE     3
#define ALIGN_PAD  256
#define SMEM_DYN   (ALIGN_PAD + NSTAGE * STG_BYTES)
#define K_ITERS    (D_N / BK)   // 16

__device__ __forceinline__ uint32_t swz(int row, int c) {
    return (uint32_t)(row * 64 + ((c ^ ((row >> 1) & 3)) * 16));
}

__device__ __forceinline__ void load_stage(uint32_t st, int bm, int bn, int k0, int tid) {
#pragma unroll
    for (int rep = 0; rep < 2; rep++) {          // A: 128 rows x 4 chunks
        int idx = tid + rep * 256;
        int row = idx >> 2, c = idx & 3;
        int grow = bm + row;
        bool va = grow < G_N;
        size_t off = va ? ((size_t)grow * D_N + k0 + c * 8) : 0;
        cpa16(st + AH_OFF + swz(row, c), g_Ah + off, va);
    }
#pragma unroll
    for (int rep = 0; rep < 2; rep++) {          // B: 128 rows x 4 chunks
        int idx = tid + rep * 256;
        int row = idx >> 2, c = idx & 3;
        size_t off = (size_t)(bn + row) * D_N + k0 + c * 8;
        cpa16(st + BH_OFF + swz(row, c), g_Bh + off, true);
    }
}

__global__ __launch_bounds__(256) void gemm_screen() {
    extern __shared__ char sm[];
    uint32_t sb = (smem_u32(sm) + (ALIGN_PAD - 1)) & ~(uint32_t)(ALIGN_PAD - 1);
    const int tid  = threadIdx.x;
    const int wid  = tid >> 5;
    const int lane = tid & 31;
    const int wm   = wid & 3;
    const int wn   = wid >> 2;
    const int bm = blockIdx.y * 128;
    const int bn = blockIdx.x * 128;

    float acc[2][8][4];
#pragma unroll
    for (int mt = 0; mt < 2; mt++)
#pragma unroll
        for (int nt = 0; nt < 8; nt++)
#pragma unroll
            for (int r = 0; r < 4; r++) acc[mt][nt][r] = 0.f;

    load_stage(sb + 0 * STG_BYTES, bm, bn, 0, tid);  cpa_commit();
    load_stage(sb + 1 * STG_BYTES, bm, bn, 32, tid); cpa_commit();
    load_stage(sb + 2 * STG_BYTES, bm, bn, 64, tid); cpa_commit();

    const int arow = wm * 32 + (lane & 7) + ((lane >> 3) & 1) * 8;
    const int acs  = (lane >> 4);
    const int brow = wn * 64 + (lane & 7) + ((lane >> 4) << 3);
    const int bcs  = ((lane >> 3) & 1);

    for (int it = 0; it < K_ITERS; it++) {
        uint32_t st = sb + (uint32_t)(it % NSTAGE) * STG_BYTES;
        if (it < K_ITERS - 3) cpa_wait2(); else cpa_wait0();
        __syncthreads();

#pragma unroll
        for (int ks = 0; ks < 2; ks++) {
            const int c0 = ks * 2;
            uint32_t ah[2][4], bh[4][4];
#pragma unroll
            for (int mt = 0; mt < 2; mt++) {
                uint32_t ao = swz(arow + mt * 16, c0 + acs);
                ldsm_x4(ah[mt][0], ah[mt][1], ah[mt][2], ah[mt][3], st + AH_OFF + ao);
            }
#pragma unroll
            for (int np = 0; np < 4; np++) {
                uint32_t bo = swz(brow + np * 16, c0 + bcs);
                ldsm_x4(bh[np][0], bh[np][1], bh[np][2], bh[np][3], st + BH_OFF + bo);
            }
#pragma unroll
            for (int mt = 0; mt < 2; mt++)
#pragma unroll
                for (int nt = 0; nt < 8; nt++)
                    mma_bf16(acc[mt][nt], ah[mt], &bh[nt >> 1][(nt & 1) * 2]);
        }
        __syncthreads();
        if (it + 3 < K_ITERS) {
            load_stage(st, bm, bn, (it + 3) * BK, tid);
            cpa_commit();
        }
    }

    const float rs = 0.04419417382415922f;
    const int mrow = (lane >> 2);
    const int ncol = (lane & 3) * 2;
#pragma unroll
    for (int mt = 0; mt < 2; mt++) {
#pragma unroll
        for (int half = 0; half < 2; half++) {
            int m = bm + wm * 32 + mt * 16 + mrow + half * 8;
            if (m < G_N) {
                float* dst = g_sim + (size_t)m * T_N + bn + wn * 64 + ncol;
#pragma unroll
                for (int nt = 0; nt < 8; nt++) {
                    float2 v;
                    v.x = acc[mt][nt][half * 2 + 0] * rs;
                    v.y = acc[mt][nt][half * 2 + 1] * rs;
                    *(float2*)(dst + nt * 8) = v;
                }
            }
        }
    }
}

// ============================================================================
// block reductions (256 threads)
// ============================================================================
__device__ __forceinline__ float blockMax256(float v) {
    __shared__ float s[8];
#pragma unroll
    for (int o = 16; o > 0; o >>= 1)
        v = fmaxf(v, __shfl_xor_sync(0xffffffffu, v, o));
    if ((threadIdx.x & 31) == 0) s[threadIdx.x >> 5] = v;
    __syncthreads();
    float r = s[0];
#pragma unroll
    for (int i = 1; i < 8; i++) r = fmaxf(r, s[i]);
    __syncthreads();
    return r;
}
__device__ __forceinline__ float blockSum256(float v) {
    __shared__ float s[8];
#pragma unroll
    for (int o = 16; o > 0; o >>= 1)
        v += __shfl_xor_sync(0xffffffffu, v, o);
    if ((threadIdx.x & 31) == 0) s[threadIdx.x >> 5] = v;
    __syncthreads();
    float r = 0.f;
#pragma unroll
    for (int i = 0; i < 8; i++) r += s[i];
    __syncthreads();
    return r;
}

// ============================================================================
// Kernel 2a: softmax_select — unchanged (126 us measured, 3x reproduced).
// ============================================================================
__global__ __launch_bounds__(256) void softmax_select(const int* __restrict__ mask,
                                                      float* __restrict__ attn_out) {
    const int g    = blockIdx.x;
    const int tid  = threadIdx.x;
    const int lane = tid & 31;
    const int w    = tid >> 5;
    const float* srow = g_sim + (size_t)g * T_N;
    const int*   mrow = mask + (size_t)g * T_N;
    float* arow = attn_out + (size_t)g * T_N;

    float sv[6]; int mv[6];
#pragma unroll
    for (int i = 0; i < 6; i++) {
        int t = tid + i * 256;
        sv[i] = srow[t];
        mv[i] = mrow[t];
    }

    if (tid < K_TOP) {
        g_tkw[g * K_TOP + tid] = 0.f;
        g_tki[g * K_TOP + tid] = 0;
    }
#pragma unroll
    for (int i = 0; i < 6; i++) arow[tid + i * 256] = 0.f;

    float lm = -INFINITY;
#pragma unroll
    for (int i = 0; i < 6; i++)
        if (mv[i]) lm = fmaxf(lm, sv[i]);
    float m = blockMax256(lm);

    if (m == -INFINITY) {
        if (tid == 0) g_cnt[g] = 0;
        return;
    }

    float lsum = 0.f;
#pragma unroll
    for (int i = 0; i < 6; i++)
        if (mv[i]) lsum += expf(sv[i] - m);
    float Z = blockSum256(lsum);

    uint32_t key[6];
#pragma unroll
    for (int i = 0; i < 6; i++) {
        uint32_t u = __float_as_uint(sv[i]);
        u = (u & 0x80000000u) ? ~u : (u | 0x80000000u);
        key[i] = mv[i] ? u : 0u;
    }

    __shared__ int hist[NH][256];
    __shared__ int wtot[8];
    __shared__ int s_b1, s_ab1, s_b2, s_ab2, s_b3;
    const int hg = w >> 1;

    // pass 1
#pragma unroll
    for (int j = 0; j < NH; j++) hist[j][tid] = 0;
    __syncthreads();
#pragma unroll
    for (int i = 0; i < 6; i++) atomicAdd(&hist[hg][key[i] >> 24], 1);
    __syncthreads();
    {
        int h = hist[0][tid] + hist[1][tid] + hist[2][tid] + hist[3][tid];
        int v = h;
#pragma unroll
        for (int off = 1; off < 32; off <<= 1) {
            int o = __shfl_down_sync(0xffffffffu, v, off);
            if (lane + off < 32) v += o;
        }
        if (lane == 0) wtot[w] = v;
        __syncthreads();
        int offs = 0;
#pragma unroll
        for (int j = 0; j < 8; j++) if (j > w) offs += wtot[j];
        int suf = v + offs;
        int nxt = suf - h;
        if (suf >= NTGT && nxt < NTGT) { s_b1 = tid; s_ab1 = nxt; }
    }
    __syncthreads();
    const uint32_t b1 = (uint32_t)s_b1;
    const int ab1 = s_ab1;

    // pass 2
#pragma unroll
    for (int j = 0; j < NH; j++) hist[j][tid] = 0;
    __syncthreads();
#pragma unroll
    for (int i = 0; i < 6; i++)
        if ((key[i] >> 24) == b1) atomicAdd(&hist[hg][(key[i] >> 16) & 0xFF], 1);
    __syncthreads();
    {
        int h = hist[0][tid] + hist[1][tid] + hist[2][tid] + hist[3][tid];
        int v = h;
#pragma unroll
        for (int off = 1; off < 32; off <<= 1) {
            int o = __shfl_down_sync(0xffffffffu, v, off);
            if (lane + off < 32) v += o;
        }
        if (lane == 0) wtot[w] = v;
        __syncthreads();
        int offs = 0;
#pragma unroll
        for (int j = 0; j < 8; j++) if (j > w) offs += wtot[j];
        int suf = v + offs;
        int nxt = suf - h;
        if (ab1 + suf >= NTGT && ab1 + nxt < NTGT) { s_b2 = tid; s_ab2 = ab1 + nxt; }
    }
    __syncthreads();
    const uint32_t thr16 = (b1 << 8) | (uint32_t)s_b2;
    const int ab2 = s_ab2;

    // pass 3
#pragma unroll
    for (int j = 0; j < NH; j++) hist[j][tid] = 0;
    __syncthreads();
#pragma unroll
    for (int i = 0; i < 6; i++)
        if ((key[i] >> 16) == thr16) atomicAdd(&hist[hg][(key[i] >> 8) & 0xFF], 1);
    __syncthreads();
    {
        int h = hist[0][tid] + hist[1][tid] + hist[2][tid] + hist[3][tid];
        int v = h;
#pragma unroll
        for (int off = 1; off < 32; off <<= 1) {
            int o = __shfl_down_sync(0xffffffffu, v, off);
            if (lane + off < 32) v += o;
        }
        if (lane == 0) wtot[w] = v;
        __syncthreads();
        int offs = 0;
#pragma unroll
        for (int j = 0; j < 8; j++) if (j > w) offs += wtot[j];
        int suf = v + offs;
        int nxt = suf - h;
        if (ab2 + suf >= NTGT && ab2 + nxt < NTGT) { s_b3 = tid; }
    }
    __syncthreads();
    const uint32_t thr24 = (thr16 << 8) | (uint32_t)s_b3;

    __shared__ int s_cnt;
    if (tid == 0) s_cnt = 0;
    __syncthreads();
#pragma unroll
    for (int i = 0; i < 6; i++) {
        if (mv[i] && (key[i] >> 8) >= thr24) {
            int p = atomicAdd(&s_cnt, 1);
            if (p < CCAP) g_cand[g * CCAP + p] = tid + i * 256;
        }
    }
    __syncthreads();
    if (tid == 0) {
        g_cnt[g] = s_cnt < CCAP ? s_cnt : CCAP;
        g_mv[g] = m;
        g_Zv[g] = Z;
    }
}

// ============================================================================
// Kernel 2b: rescore_wave — split-k waves for 4 blocks/SM occupancy.
// Stage k[0:256) of ALL 48 candidates (48 KB, 16B swizzled cp.async), run all
// 48 chains over that half, re-stage k[256:512) into the SAME buffer, continue
// the chains with the SAME register accumulator. The per-candidate summation
// is one sequential k-ascending FMA chain — bit-identical to the order
// verified at 2.19e-7 eight times. Then exact rank + scatter (unchanged).
//   dynamic smem: s_a[512] + s_half[CCAP*64 float4] = 51200 B -> 4 blocks/SM
// ============================================================================
__global__ __launch_bounds__(256) void rescore_wave(float* __restrict__ attn_out,
                                                    const float* __restrict__ tg,
                                                    const float* __restrict__ tfb) {
    extern __shared__ float dynsm[];
    float*  s_a    = dynsm;                      // 512 floats (tg row)
    float4* s_half = (float4*)(dynsm + 512);     // CCAP*64 float4 (one k-half)

    const int g   = blockIdx.x;
    const int tid = threadIdx.x;
    const int nC  = g_cnt[g];
    if (nC == 0) return;

    __shared__ int s_ci[CCAP];
    if (tid < CCAP) s_ci[tid] = (tid < nC) ? g_cand[g * CCAP + tid] : 0;
    if (tid < 128)
        cpa16(smem_u32(s_a + tid * 4), tg + (size_t)g * D_N + tid * 4, true);
    __syncthreads();   // s_ci visible before row staging uses it

    float acc = 0.f;
    __shared__ float s_ex[CCAP];

#pragma unroll
    for (int h = 0; h < 2; h++) {
        // stage k-half h: CCAP rows x 64 float4 (coalesced, float4 swizzle)
#pragma unroll
        for (int j = 0; j < (CCAP * 64) / 256; j++) {   // 12 iterations
            int lin = tid + j * 256;
            int r = lin >> 6, q = lin & 63;
            bool va = r < nC;
            int c = s_ci[r];
            cpa16(smem_u32(s_half + r * 64 + (q ^ (r & 7))),
                  tfb + (size_t)(va ? c : 0) * D_N + h * 256 + q * 4, va);
        }
        cpa_commit();
        cpa_wait0();
        __syncthreads();

        // continue the sequential chain over this half (ascending k)
        if (tid < nC) {
            const float4* row = s_half + tid * 64;
            const float*  a   = s_a + h * 256;
            const int cx = tid & 7;
#pragma unroll 4
            for (int q = 0; q < 64; q++) {
                float4 v = row[q ^ cx];
                const float* a4 = a + q * 4;
                acc = fmaf(a4[0], v.x, acc);
                acc = fmaf(a4[1], v.y, acc);
                acc = fmaf(a4[2], v.z, acc);
                acc = fmaf(a4[3], v.w, acc);
            }
        }
        __syncthreads();   // chains done before the buffer is overwritten
    }
    if (tid < nC) s_ex[tid] = acc / 22.627416997969522f;
    __syncthreads();

    // ---- exact rank among candidates: (value desc, index asc) ----
    __shared__ int   s_rank[CCAP];
    __shared__ float s_x[CCAP];
    __shared__ float s_mex, s_S;
    if (tid < CCAP) {
        s_x[tid] = 0.f;
        if (tid < nC) {
            float exi = s_ex[tid]; int ci = s_ci[tid];
            int rank = 0;
            for (int j = 0; j < nC; j++) {
                float exj = s_ex[j];
                if (exj > exi || (exj == exi && s_ci[j] < ci)) rank++;
            }
            s_rank[tid] = rank;
            if (rank == 0) s_mex = exi;
        }
    }
    __syncthreads();

    const float m = g_mv[g];
    const float Z = g_Zv[g];
    const float mex = s_mex;
    const float Zp = Z * expf(m - mex);   // Z re-referenced to exact max
    if (tid < nC && s_rank[tid] < K_TOP)
        s_x[tid] = expf(s_ex[tid] - mex) / Zp;   // ref: a = e/Z
    __syncthreads();
    if (tid == 0) {
        float S = 0.f;
#pragma unroll
        for (int j = 0; j < CCAP; j++) S += s_x[j];
        s_S = S;
    }
    __syncthreads();

    const float den = s_S + 1e-8f;    // ref: attn / (sum + 1e-8)
    if (tid < nC && s_rank[tid] < K_TOP) {
        float outx = s_x[tid] / den;
        int c = s_ci[tid];
        attn_out[(size_t)g * T_N + c] = outx;   // row pre-zeroed by select
        g_tki[g * K_TOP + s_rank[tid]] = c;
        g_tkw[g * K_TOP + s_rank[tid]] = outx;
    }
}

// ============================================================================
// Kernel 3a: transpose tf_expr [B,T] -> g_tfT [T,B]
// ============================================================================
__global__ void transpose_tf(const float* __restrict__ tf) {
    __shared__ float tile[32][33];
    int bx = blockIdx.x * 32;
    int by = blockIdx.y * 32;
#pragma unroll
    for (int r = 0; r < 32; r += 8)
        tile[threadIdx.y + r][threadIdx.x] =
            tf[(size_t)(by + threadIdx.y + r) * T_N + bx + threadIdx.x];
    __syncthreads();
#pragma unroll
    for (int r = 0; r < 32; r += 8)
        g_tfT[(size_t)(bx + threadIdx.y + r) * B_N + by + threadIdx.x] =
            tile[threadIdx.x][threadIdx.y + r];
}

// ============================================================================
// Kernel 3b: sparse combine  out[b,g] = scale * sum_j w[g,j]*tfT[idx[g,j], b]
// ============================================================================
__global__ __launch_bounds__(256) void combine(const float* __restrict__ scale,
                                               float* __restrict__ outS) {
    const int g0 = blockIdx.x * 8;
    const int b  = threadIdx.x;
    __shared__ int   si[8][K_TOP];
    __shared__ float sw[8][K_TOP];
    {
        int q = threadIdx.x >> 5, j = threadIdx.x & 31;
        si[q][j] = g_tki[(g0 + q) * K_TOP + j];
        sw[q][j] = g_tkw[(g0 + q) * K_TOP + j];
    }
    __syncthreads();

    float acc[8];
#pragma unroll
    for (int q = 0; q < 8; q++) acc[q] = 0.f;

#pragma unroll 4
    for (int j = 0; j < K_TOP; j++) {
#pragma unroll
        for (int q = 0; q < 8; q++)
            acc[q] = fmaf(sw[q][j], g_tfT[si[q][j] * B_N + b], acc[q]);
    }

    float sc = scale[0];
    float4 o0 = make_float4(sc * acc[0], sc * acc[1], sc * acc[2], sc * acc[3]);
    float4 o1 = make_float4(sc * acc[4], sc * acc[5], sc * acc[6], sc * acc[7]);
    float* dst = outS + (size_t)b * G_N + g0;
    *(float4*)dst = o0;
    *(float4*)(dst + 4) = o1;
}

// ============================================================================
// launch
// ============================================================================
extern "C" void kernel_launch(void* const* d_in, const int* in_sizes, int n_in,
                              void* d_out, int out_size) {
    const float* tg_dec     = (const float*)d_in[0];
    const float* tf_base    = (const float*)d_in[1];
    const float* tf_expr    = (const float*)d_in[2];
    const int*   motif_mask = (const int*)d_in[3];
    const float* scale      = (const float*)d_in[4];

    float* out        = (float*)d_out;
    float* out_scalar = out;                          // [B, G]
    float* out_attn   = out + (size_t)B_N * G_N;      // [G, T]

    const int resc_dyn = (512 + CCAP * 256) * (int)sizeof(float);  // 51200 B

    cudaFuncSetAttribute(gemm_screen,
                         cudaFuncAttributeMaxDynamicSharedMemorySize, SMEM_DYN);
    cudaFuncSetAttribute(rescore_wave,
                         cudaFuncAttributeMaxDynamicSharedMemorySize, resc_dyn);

    // bf16 cast of screening operands
    {
        size_t total = (size_t)G_N * D_N + (size_t)T_N * D_N;
        int blocks = (int)((total + 255) / 256);
        cast_bf16<<<blocks, 256>>>(tg_dec, tf_base);
    }
    // transpose tf_expr (independent; needed by combine)
    {
        dim3 blk(32, 8), grd(T_N / 32, B_N / 32);
        transpose_tf<<<grd, blk>>>(tf_expr);
    }
    // screening GEMM (single bf16 HMMA product)
    {
        dim3 grd(T_N / 128, (G_N + 127) / 128);   // (12, 157)
        gemm_screen<<<grd, 256, SMEM_DYN>>>();
    }
    // high-occupancy softmax + radix select + dense zeroing
    softmax_select<<<G_N, 256>>>(motif_mask, out_attn);
    // split-k wave rescore (4 blocks/SM) + scatter
    rescore_wave<<<G_N, 256, resc_dyn>>>(out_attn, tg_dec, tf_base);
    // sparse weighted combine
    combine<<<G_N / 8, 256>>>(scale, out_scalar);
}